// round 16
// baseline (speedup 1.0000x reference)
#include <cuda_runtime.h>
#include <cstdint>

#define HH 192
#define WW 192
#define BB 4
#define HWW (HH*WW)

// ---------------- scratch buffers (device globals; no allocation) ----------
__device__ float g_c1a[BB*64*HWW];
__device__ float g_c1b[BB*64*HWW];
__device__ float g_c2a[BB*128*HWW];
__device__ float g_c2b[BB*128*HWW];
__device__ float g_redir[BB*32*HWW];
__device__ float g_corr[BB*441*HWW];

__device__ __forceinline__ float lrelu(float x) { return x >= 0.f ? x : 0.1f * x; }

__device__ __forceinline__ void cp_async4(uint32_t dst, const void* src, bool p) {
    asm volatile("cp.async.ca.shared.global [%0], [%1], 4, %2;"
                 :: "r"(dst), "l"(src), "r"(p ? 4 : 0));
}
__device__ __forceinline__ void cp_async16(uint32_t dst, const void* src, bool p) {
    asm volatile("cp.async.cg.shared.global [%0], [%1], 16, %2;"
                 :: "r"(dst), "l"(src), "r"(p ? 16 : 0));
}
__device__ __forceinline__ void cp_commit() {
    asm volatile("cp.async.commit_group;");
}
__device__ __forceinline__ void cp_wait0() {
    asm volatile("cp.async.wait_group 0;");
}

// ---------------- 3x3 conv + bias + leaky relu (v4, proven) -----------------
#define SIN4 (4*34*36)       // floats per input buffer (4896)

template<int CIN, int COUT>
__global__ __launch_bounds__(256, 3)
void conv3x3_v4(const float* __restrict__ in, const float* __restrict__ wgt,
                const float* __restrict__ bias, float* __restrict__ out)
{
    extern __shared__ float smem[];   // [2*SIN4 inputs][CIN*72 weights]
    float* s_w = smem + 2*SIN4;

    const int x0 = blockIdx.x * 32;
    const int y0 = blockIdx.y * 32;
    const int bz = blockIdx.z;
    const int b   = bz / (COUT/8);
    const int co0 = (bz % (COUT/8)) * 8;
    const int tx = threadIdx.x, ty = threadIdx.y;
    const int tid = ty*16 + tx;

    uint32_t smem_u32 = (uint32_t)__cvta_generic_to_shared(smem);

    int  soff[5];  int goff[5];
    bool inb[5];   bool wr[5];
#pragma unroll
    for (int k = 0; k < 5; k++) {
        int i = tid + k*256;
        bool ok = (i < 34*34);
        int ii = ok ? i : 0;
        int ly = ii / 34, lx = ii % 34;
        int gy = y0 + ly - 1, gx = x0 + lx - 1;
        bool v = ok && (gy >= 0) && (gy < HH) && (gx >= 0) && (gx < WW);
        soff[k] = ly*36 + lx;
        goff[k] = v ? ((b*CIN)*HH + gy)*WW + gx : 0;
        inb[k]  = v;
        wr[k]   = ok;
    }

    auto stage = [&](int buf, int c0) {
        uint32_t in_dst = smem_u32 + buf*(SIN4*4);
#pragma unroll
        for (int k = 0; k < 5; k++) {
            if (wr[k]) {
                const float* src = in + goff[k] + c0*HWW;
                uint32_t d = in_dst + soff[k]*4;
#pragma unroll
                for (int c = 0; c < 4; c++)
                    cp_async4(d + c*(34*36*4), src + c*HWW, inb[k]);
            }
        }
        cp_commit();
    };

    stage(0, 0);

    for (int i = tid; i < CIN*72; i += 256) {
        int c = i / 72, r = i % 72;
        int k = r / 8,  o = r % 8;
        s_w[i] = wgt[((co0 + o)*CIN + c)*9 + k];
    }

    float acc[8][2][2];
#pragma unroll
    for (int o = 0; o < 8; o++)
#pragma unroll
        for (int py = 0; py < 2; py++)
#pragma unroll
            for (int px = 0; px < 2; px++) acc[o][py][px] = 0.f;

    const int NCH = CIN/4;
    for (int ci = 0; ci < NCH; ci++) {
        cp_wait0();
        __syncthreads();
        if (ci + 1 < NCH) stage((ci+1) & 1, (ci+1)*4);

        const float* s_in = smem + (ci & 1)*SIN4;
        const float* wbase = s_w + ci*4*72;

#pragma unroll
        for (int c = 0; c < 4; c++) {
            float p[4][4];
#pragma unroll
            for (int r = 0; r < 4; r++)
#pragma unroll
                for (int q = 0; q < 4; q++)
                    p[r][q] = s_in[c*(34*36) + (ty*2 + r)*36 + tx*2 + q];
#pragma unroll
            for (int ky = 0; ky < 3; ky++) {
#pragma unroll
                for (int kx = 0; kx < 3; kx++) {
                    const float4 wa = *(const float4*)&wbase[c*72 + (ky*3+kx)*8 + 0];
                    const float4 wb = *(const float4*)&wbase[c*72 + (ky*3+kx)*8 + 4];
                    const float w[8] = {wa.x, wa.y, wa.z, wa.w, wb.x, wb.y, wb.z, wb.w};
#pragma unroll
                    for (int py = 0; py < 2; py++) {
#pragma unroll
                        for (int px = 0; px < 2; px++) {
                            const float v = p[py+ky][px+kx];
#pragma unroll
                            for (int o = 0; o < 8; o++)
                                acc[o][py][px] += v * w[o];
                        }
                    }
                }
            }
        }
    }

#pragma unroll
    for (int o = 0; o < 8; o++) {
        const float bv = __ldg(&bias[co0 + o]);
#pragma unroll
        for (int py = 0; py < 2; py++) {
            const int y = y0 + ty*2 + py;
            const int x = x0 + tx*2;
            float2 v;
            v.x = lrelu(acc[o][py][0] + bv);
            v.y = lrelu(acc[o][py][1] + bv);
            *(float2*)&out[(((b*COUT) + co0 + o)*HH + y)*WW + x] = v;
        }
    }
}

// ---------------- 1x1 redir conv + lrelu -----------------------------------
__global__ __launch_bounds__(256)
void redir_conv(const float* __restrict__ in, const float* __restrict__ wgt,
                const float* __restrict__ bias, float* __restrict__ out)
{
    const int b  = blockIdx.y;
    const int p0 = blockIdx.x * 64;
    const int tid = threadIdx.x;

    __shared__ float s[128*64];
    for (int i = tid; i < 128*64; i += 256) {
        int c = i >> 6, p = i & 63;
        s[c*64 + p] = in[(b*128 + c)*HWW + p0 + p];
    }
    __syncthreads();

    for (int oi = tid; oi < 32*64; oi += 256) {
        const int co = oi >> 6;
        const int p  = oi & 63;
        float sum = bias[co];
#pragma unroll 16
        for (int c = 0; c < 128; c++)
            sum += s[c*64 + p] * __ldg(&wgt[co*128 + c]);
        out[(b*32 + co)*HWW + p0 + p] = lrelu(sum);
    }
}

// ---------------- correlation (patch 21, dil 2) + lrelu (v8) ----------------
// 288 threads, 2 blocks/SM (18 warps/SM). Lane tile 8px x 8dx, SWZ smem
// (proven v6 mapping). BOTH A and B are streamed per-dy in 4 x 32-channel
// chunks, double-buffered with cp.async (A no longer resident -> smem
// footprint 108 KB -> 2 co-resident blocks for latency hiding).
// Buffer layout (float4): A chunk [32][SAW] then B chunk [32][SBW].
#define SBW 60     // float4 per B row (240 floats)
#define SAW 48     // float4 per A row (192 floats)
#define CHUNK_A  (32*SAW)               // 1536 f4
#define CHUNK_B  (32*SBW)               // 1920 f4
#define CHUNK_F4 (CHUNK_A + CHUNK_B)    // 3456 f4
#define CHUNK_FLOATS (CHUNK_F4*4)       // 13824 floats = 55296 B
__device__ __forceinline__ int SWZ(int v) { return v ^ ((v >> 3) & 1); }

__global__ __launch_bounds__(288, 2)
void corr_v8(const float* __restrict__ A, const float* __restrict__ Bm,
             float* __restrict__ out)
{
    extern __shared__ float smem[];

    const int y = blockIdx.x;
    const int b = blockIdx.y;
    const int tid = threadIdx.x;
    const int warp = tid >> 5;
    const int lane = tid & 31;
    const int cq  = lane >> 3;         // channel eighth within chunk (8 ch)
    const int sub = lane & 7;          // px sub-tile 0..7
    const int dxg   = warp % 3;        // dx group: 0..7, 8..15, 16..20
    const int pxblk = warp / 3;        // 3 blocks of 64 px
    const int px0 = pxblk*64 + sub*8;
    const int dx0 = dxg*8;
    const int va  = 16*pxblk + 2*sub;  // A float4 base within row
    const int vb  = va + 4*dxg;        // B float4 base within row

    uint32_t smem_u32 = (uint32_t)__cvta_generic_to_shared(smem);
    const uint32_t bufu[2] = { smem_u32, smem_u32 + CHUNK_FLOATS*4 };

    const float inv_c = 1.0f / 128.0f;
    const float* Ab = A  + (b*128)*HWW + y*WW;
    const float* Bb = Bm + (b*128)*HWW;

    // stage chunk (channels ch0..ch0+31): A row y + B row ry
    auto stage_chunk = [&](int buf, const float* Brow, int ch0) {
        const uint32_t dst = bufu[buf];
        const float* Abase = Ab + ch0*HWW;
        for (int i = tid; i < CHUNK_A; i += 288) {
            int c = i / SAW, v = i % SAW;
            cp_async16(dst + (c*SAW + SWZ(v))*16, Abase + c*HWW + v*4, true);
        }
        const float* Bbase = Brow + ch0*HWW;
        for (int i = tid; i < CHUNK_B; i += 288) {
            int c = i / SBW, v = i % SBW;
            bool inb = (v >= 5) && (v <= 52);      // gx = 4v-20 fully in range
            cp_async16(dst + (CHUNK_A + c*SBW + SWZ(v))*16,
                       Bbase + c*HWW + (inb ? 4*v - 20 : 0), inb);
        }
        cp_commit();
    };

    bool pending = false;   // chunk0 of current dy already staged into buf0?

    for (int dy = 0; dy < 21; dy++) {
        const int ry = y + dy*2 - 20;
        if (ry < 0 || ry >= HH) {
            const float4 z = {0.f, 0.f, 0.f, 0.f};
            for (int i = tid; i < 21*48; i += 288) {
                int dx = i / 48, v = i % 48;
                *(float4*)&out[((b*441 + dy*21 + dx)*HH + y)*WW + v*4] = z;
            }
            continue;
        }
        const float* Brow = Bb + ry*WW;
        if (!pending) stage_chunk(0, Brow, 0);

        float acc[8][8];
#pragma unroll
        for (int d = 0; d < 8; d++)
#pragma unroll
            for (int p = 0; p < 8; p++) acc[d][p] = 0.f;

#pragma unroll
        for (int j = 0; j < 4; j++) {
            cp_wait0();          // chunk j arrived
            __syncthreads();     // all warps done with the buffer we overwrite
            if (j < 3) {
                stage_chunk((j+1) & 1, Brow, (j+1)*32);
            } else {
                const int ry2 = ry + 2;
                if (dy < 20 && ry2 < HH) {
                    stage_chunk(0, Bb + ry2*WW, 0);
                    pending = true;
                } else {
                    pending = false;
                }
            }

            const float4* pa = (const float4*)(smem + (j & 1)*CHUNK_FLOATS)
                               + (cq*8)*SAW;
            const float4* pb = (const float4*)(smem + (j & 1)*CHUNK_FLOATS)
                               + CHUNK_A + (cq*8)*SBW;
#pragma unroll 2
            for (int cc = 0; cc < 8; cc++) {
                const float4 a0 = pa[cc*SAW + SWZ(va)];
                const float4 a1 = pa[cc*SAW + SWZ(va+1)];
                const float a[8] = {a0.x,a0.y,a0.z,a0.w, a1.x,a1.y,a1.z,a1.w};
                float bv[24];
#pragma unroll
                for (int t = 0; t < 6; t++) {
                    const float4 tt = pb[cc*SBW + SWZ(vb + t)];
                    bv[4*t+0] = tt.x; bv[4*t+1] = tt.y;
                    bv[4*t+2] = tt.z; bv[4*t+3] = tt.w;
                }
#pragma unroll
                for (int d = 0; d < 8; d++)
#pragma unroll
                    for (int p = 0; p < 8; p++)
                        acc[d][p] += a[p] * bv[2*d + p];
            }
        }

        // combine 4 lane-quarter partials (lanes l, l+8, l+16, l+24)
#pragma unroll
        for (int d = 0; d < 8; d++)
#pragma unroll
            for (int p = 0; p < 8; p++) {
                float v = acc[d][p];
                v += __shfl_down_sync(0xffffffffu, v, 16);
                v += __shfl_down_sync(0xffffffffu, v, 8);
                acc[d][p] = v;
            }

        if (cq == 0) {
#pragma unroll
            for (int d = 0; d < 8; d++) {
                const int dx = dx0 + d;
                if (dx < 21) {
                    float* o = &out[((b*441 + dy*21 + dx)*HH + y)*WW + px0];
                    float4 v0, v1;
                    v0.x = lrelu(acc[d][0] * inv_c);
                    v0.y = lrelu(acc[d][1] * inv_c);
                    v0.z = lrelu(acc[d][2] * inv_c);
                    v0.w = lrelu(acc[d][3] * inv_c);
                    v1.x = lrelu(acc[d][4] * inv_c);
                    v1.y = lrelu(acc[d][5] * inv_c);
                    v1.z = lrelu(acc[d][6] * inv_c);
                    v1.w = lrelu(acc[d][7] * inv_c);
                    *(float4*)(o)     = v0;
                    *(float4*)(o + 4) = v1;
                }
            }
        }
    }
}

// ---------------- final 3x3 conv (v3: cp.async double-buffer) ---------------
#define FIN_SZ (8*34*36)     // floats per input buffer (9792)

__global__ __launch_bounds__(256)
void final_conv_v3(const float* __restrict__ redir, const float* __restrict__ corr,
                   const float* __restrict__ wgt, float* __restrict__ out)
{
    extern __shared__ float smem[];   // [2*FIN_SZ inputs][480*18 weights]
    float* sw = smem + 2*FIN_SZ;      // sw[c*18 + k*2 + o]

    const int x0 = blockIdx.x * 32;
    const int y0 = blockIdx.y * 32;
    const int b  = blockIdx.z;
    const int tx = threadIdx.x, ty = threadIdx.y;
    const int tid = ty*16 + tx;

    uint32_t smem_u32 = (uint32_t)__cvta_generic_to_shared(smem);

    int  soff[5];  int spat[5];
    bool inb[5];   bool wr[5];
#pragma unroll
    for (int k = 0; k < 5; k++) {
        int i = tid + k*256;
        bool ok = (i < 34*34);
        int ii = ok ? i : 0;
        int ly = ii / 34, lx = ii % 34;
        int gy = y0 + ly - 1, gx = x0 + lx - 1;
        bool v = ok && (gy >= 0) && (gy < HH) && (gx >= 0) && (gx < WW);
        soff[k] = ly*36 + lx;
        spat[k] = v ? gy*WW + gx : 0;
        inb[k]  = v;
        wr[k]   = ok;
    }

    auto stage = [&](int buf, int c0) {
        const int cn = (473 - c0) < 8 ? (473 - c0) : 8;
        const float* base = (c0 < 32) ? (redir + (b*32 + c0)*HWW)
                                      : (corr + (b*441 + (c0 - 32))*HWW);
        uint32_t in_dst = smem_u32 + buf*(FIN_SZ*4);
#pragma unroll
        for (int k = 0; k < 5; k++) {
            if (wr[k]) {
                const float* p = base + spat[k];
                uint32_t d = in_dst + soff[k]*4;
#pragma unroll
                for (int c = 0; c < 8; c++)
                    cp_async4(d + c*(34*36*4), p + c*HWW, inb[k] && (c < cn));
            }
        }
        cp_commit();
    };

    stage(0, 0);

    for (int i = tid; i < 480*18; i += 256) {
        int c = i / 18, r = i % 18;
        int kk = r >> 1, o = r & 1;
        sw[i] = (c < 473) ? wgt[(o*473 + c)*9 + kk] : 0.f;
    }

    float acc[2][2][2];
#pragma unroll
    for (int o = 0; o < 2; o++)
#pragma unroll
        for (int py = 0; py < 2; py++)
#pragma unroll
            for (int px = 0; px < 2; px++) acc[o][py][px] = 0.f;

    const int NCH = 60;   // ceil(473/8)
    for (int ci = 0; ci < NCH; ci++) {
        cp_wait0();
        __syncthreads();
        if (ci + 1 < NCH) stage((ci+1) & 1, (ci+1)*8);

        const float* s_in = smem + (ci & 1)*FIN_SZ;
        const float* wb = sw + ci*8*18;

#pragma unroll
        for (int c = 0; c < 8; c++) {
            float p[4][4];
#pragma unroll
            for (int r = 0; r < 4; r++)
#pragma unroll
                for (int q = 0; q < 4; q++)
                    p[r][q] = s_in[c*(34*36) + (ty*2 + r)*36 + tx*2 + q];
#pragma unroll
            for (int ky = 0; ky < 3; ky++) {
#pragma unroll
                for (int kx = 0; kx < 3; kx++) {
                    const float w0 = wb[c*18 + (ky*3+kx)*2 + 0];
                    const float w1 = wb[c*18 + (ky*3+kx)*2 + 1];
#pragma unroll
                    for (int py = 0; py < 2; py++) {
#pragma unroll
                        for (int px = 0; px < 2; px++) {
                            const float v = p[py+ky][px+kx];
                            acc[0][py][px] += v * w0;
                            acc[1][py][px] += v * w1;
                        }
                    }
                }
            }
        }
    }

#pragma unroll
    for (int o = 0; o < 2; o++) {
#pragma unroll
        for (int py = 0; py < 2; py++) {
            const int y = y0 + ty*2 + py;
            const int x = x0 + tx*2;
            float2 v;
            v.x = acc[o][py][0];
            v.y = acc[o][py][1];
            *(float2*)&out[((b*2 + o)*HH + y)*WW + x] = v;
        }
    }
}

// ---------------- launch -----------------------------------------------------
extern "C" void kernel_launch(void* const* d_in, const int* in_sizes, int n_in,
                              void* d_out, int out_size)
{
    const float* pred    = (const float*)d_in[0];
    const float* ref     = (const float*)d_in[1];
    const float* conv1_w = (const float*)d_in[2];
    const float* conv1_b = (const float*)d_in[3];
    const float* conv2_w = (const float*)d_in[4];
    const float* conv2_b = (const float*)d_in[5];
    const float* redir_w = (const float*)d_in[6];
    const float* redir_b = (const float*)d_in[7];
    const float* pred_w  = (const float*)d_in[8];
    float* out = (float*)d_out;

    float *c1a, *c1b, *c2a, *c2b, *rdr, *cor;
    cudaGetSymbolAddress((void**)&c1a, g_c1a);
    cudaGetSymbolAddress((void**)&c1b, g_c1b);
    cudaGetSymbolAddress((void**)&c2a, g_c2a);
    cudaGetSymbolAddress((void**)&c2b, g_c2b);
    cudaGetSymbolAddress((void**)&rdr, g_redir);
    cudaGetSymbolAddress((void**)&cor, g_corr);

    const int conv_smem = (2*SIN4 + 64*72) * (int)sizeof(float); // 57600
    cudaFuncSetAttribute(conv3x3_v4<64,64>,  cudaFuncAttributeMaxDynamicSharedMemorySize, conv_smem);
    cudaFuncSetAttribute(conv3x3_v4<64,128>, cudaFuncAttributeMaxDynamicSharedMemorySize, conv_smem);

    // conv1 (64->64) on pred and ref
    {
        dim3 grid(WW/32, HH/32, BB * (64/8));
        dim3 blk(16, 16);
        conv3x3_v4<64,64><<<grid, blk, conv_smem>>>(pred, conv1_w, conv1_b, c1a);
        conv3x3_v4<64,64><<<grid, blk, conv_smem>>>(ref,  conv1_w, conv1_b, c1b);
    }
    // conv2 (64->128)
    {
        dim3 grid(WW/32, HH/32, BB * (128/8));
        dim3 blk(16, 16);
        conv3x3_v4<64,128><<<grid, blk, conv_smem>>>(c1a, conv2_w, conv2_b, c2a);
        conv3x3_v4<64,128><<<grid, blk, conv_smem>>>(c1b, conv2_w, conv2_b, c2b);
    }
    // redir 1x1 (128->32)
    {
        dim3 grid(HWW/64, BB);
        redir_conv<<<grid, 256>>>(c2a, redir_w, redir_b, rdr);
    }
    // correlation
    {
        const int smem_bytes = 2*CHUNK_FLOATS * (int)sizeof(float); // 110592
        cudaFuncSetAttribute(corr_v8, cudaFuncAttributeMaxDynamicSharedMemorySize, smem_bytes);
        dim3 grid(HH, BB);
        corr_v8<<<grid, 288, smem_bytes>>>(c2a, c2b, cor);
    }
    // final conv (473->2)
    {
        const int fin_smem = (2*FIN_SZ + 480*18) * (int)sizeof(float); // 112896
        cudaFuncSetAttribute(final_conv_v3, cudaFuncAttributeMaxDynamicSharedMemorySize, fin_smem);
        dim3 grid(WW/32, HH/32, BB);
        dim3 blk(16, 16);
        final_conv_v3<<<grid, blk, fin_smem>>>(rdr, cor, pred_w, out);
    }
}